// round 1
// baseline (speedup 1.0000x reference)
#include <cuda_runtime.h>
#include <math.h>

// Problem constants
#define Bv 1024
#define Tv 16
#define Vv 8000
#define Ev 256
#define Hv 512
#define H3 (3 * Hv)

// ---------------- scratch (static device globals; no runtime alloc) ---------
__device__ float g_X[Tv * Bv * Ev];        // gathered inputs (t*B+b, E)     16 MB
__device__ float g_GI[Tv * Bv * H3];       // input gates for all steps      96 MB
__device__ float g_GH[Bv * H3];            // hidden gates, one step          6 MB
__device__ float g_Hall[Tv * Bv * Hv];     // hidden states all steps        32 MB

// ---------------- gather: xs[t] = embed[SOS or target[:, t-1]] --------------
__global__ void gather_x(const float* __restrict__ embed,
                         const int* __restrict__ target) {
    int row = blockIdx.x;              // row = t*B + b
    int t = row >> 10;                 // / B
    int b = row & (Bv - 1);
    int idx = (t == 0) ? 0 : target[b * Tv + (t - 1)];
    const float4* src = (const float4*)(embed + (size_t)idx * Ev);
    float4* dst = (float4*)(g_X + (size_t)row * Ev);
    dst[threadIdx.x] = src[threadIdx.x];   // 64 threads * float4 = 256 floats
}

// ---------------- SGEMM (NT): C[m,n] = sum_k A[m,k]*W[n,k] + bias[n] --------
// A: M x K row-major, W: N x K row-major. M % 128 == 0, K % 8 == 0 required.
// remap != 0: output row m=(t*B+b) is written to row (b*T+t) (logits layout).
__global__ __launch_bounds__(256)
void sgemm_nt(const float* __restrict__ A, const float* __restrict__ W,
              const float* __restrict__ bias, float* __restrict__ C,
              int M, int N, int K, int remap) {
    __shared__ float As[8][128];
    __shared__ float Ws[8][128];

    const int tid = threadIdx.x;
    const int bm = blockIdx.y, bn = blockIdx.x;

    // load indices: 256 threads, each one float4; 128 rows x 8 k
    const int loadRow = tid >> 1;
    const int loadK   = (tid & 1) * 4;
    const float* Ablk = A + (size_t)(bm * 128 + loadRow) * K + loadK;
    const int wRow = bn * 128 + loadRow;
    const bool wValid = (wRow < N);
    const float* Wblk = W + (size_t)wRow * K + loadK;

    // compute indices: 16x16 threads, 8x8 micro-tile each
    const int tx = tid & 15;
    const int ty = tid >> 4;
    const int cm = ty * 8;
    const int cn = tx * 8;

    float acc[8][8];
#pragma unroll
    for (int i = 0; i < 8; i++)
#pragma unroll
        for (int j = 0; j < 8; j++) acc[i][j] = 0.f;

    for (int k0 = 0; k0 < K; k0 += 8) {
        float4 av = *(const float4*)(Ablk + k0);
        float4 wv = wValid ? *(const float4*)(Wblk + k0)
                           : make_float4(0.f, 0.f, 0.f, 0.f);
        __syncthreads();
        As[loadK + 0][loadRow] = av.x;
        As[loadK + 1][loadRow] = av.y;
        As[loadK + 2][loadRow] = av.z;
        As[loadK + 3][loadRow] = av.w;
        Ws[loadK + 0][loadRow] = wv.x;
        Ws[loadK + 1][loadRow] = wv.y;
        Ws[loadK + 2][loadRow] = wv.z;
        Ws[loadK + 3][loadRow] = wv.w;
        __syncthreads();
#pragma unroll
        for (int kk = 0; kk < 8; kk++) {
            float4 a0 = *(const float4*)&As[kk][cm];
            float4 a1 = *(const float4*)&As[kk][cm + 4];
            float4 b0 = *(const float4*)&Ws[kk][cn];
            float4 b1 = *(const float4*)&Ws[kk][cn + 4];
            float ra[8] = {a0.x, a0.y, a0.z, a0.w, a1.x, a1.y, a1.z, a1.w};
            float rb[8] = {b0.x, b0.y, b0.z, b0.w, b1.x, b1.y, b1.z, b1.w};
#pragma unroll
            for (int i = 0; i < 8; i++)
#pragma unroll
                for (int j = 0; j < 8; j++) acc[i][j] += ra[i] * rb[j];
        }
    }

#pragma unroll
    for (int i = 0; i < 8; i++) {
        int m = bm * 128 + cm + i;
        int row = remap ? ((m & (Bv - 1)) * Tv + (m >> 10)) : m;
        float* crow = C + (size_t)row * N;
#pragma unroll
        for (int j = 0; j < 8; j++) {
            int n = bn * 128 + cn + j;
            if (n < N) crow[n] = acc[i][j] + bias[n];
        }
    }
}

// ---------------- GRU gate math ---------------------------------------------
__device__ __forceinline__ float sigm(float x) { return 1.f / (1.f + expf(-x)); }

__global__ void gru_gates(const float* __restrict__ gi,
                          const float* __restrict__ gh,
                          const float* __restrict__ hprev,
                          float* __restrict__ hout) {
    int j = blockIdx.x * blockDim.x + threadIdx.x;   // < B*H
    int b = j >> 9;          // / H
    int c = j & (Hv - 1);
    const float* gib = gi + (size_t)b * H3;
    const float* ghb = gh + (size_t)b * H3;
    float r = sigm(gib[c] + ghb[c]);
    float z = sigm(gib[Hv + c] + ghb[Hv + c]);
    float n = tanhf(gib[2 * Hv + c] + r * ghb[2 * Hv + c]);
    float h = hprev[j];
    hout[j] = (1.f - z) * n + z * h;
}

// ---------------- in-place log-softmax over rows of V ------------------------
__global__ __launch_bounds__(256)
void logsoftmax_rows(float* __restrict__ out) {
    __shared__ float red[256];
    const int tid = threadIdx.x;
    float* p = out + (size_t)blockIdx.x * Vv;

    float m = -INFINITY;
    for (int i = tid; i < Vv; i += 256) m = fmaxf(m, p[i]);
    red[tid] = m;
    __syncthreads();
    for (int s = 128; s > 0; s >>= 1) {
        if (tid < s) red[tid] = fmaxf(red[tid], red[tid + s]);
        __syncthreads();
    }
    m = red[0];
    __syncthreads();

    float sum = 0.f;
    for (int i = tid; i < Vv; i += 256) sum += expf(p[i] - m);
    red[tid] = sum;
    __syncthreads();
    for (int s = 128; s > 0; s >>= 1) {
        if (tid < s) red[tid] += red[tid + s];
        __syncthreads();
    }
    float lse = m + logf(red[0]);

    for (int i = tid; i < Vv; i += 256) p[i] -= lse;
}

// ---------------- launch ------------------------------------------------------
extern "C" void kernel_launch(void* const* d_in, const int* in_sizes, int n_in,
                              void* d_out, int out_size) {
    const float* context = (const float*)d_in[0];
    const int*   target  = (const int*)  d_in[1];
    const float* embed   = (const float*)d_in[2];
    const float* W_ih    = (const float*)d_in[3];
    const float* W_hh    = (const float*)d_in[4];
    const float* b_ih    = (const float*)d_in[5];
    const float* b_hh    = (const float*)d_in[6];
    const float* out_W   = (const float*)d_in[7];
    const float* out_b   = (const float*)d_in[8];
    float* out = (float*)d_out;

    float *pX, *pGI, *pGH, *pHall;
    cudaGetSymbolAddress((void**)&pX, g_X);
    cudaGetSymbolAddress((void**)&pGI, g_GI);
    cudaGetSymbolAddress((void**)&pGH, g_GH);
    cudaGetSymbolAddress((void**)&pHall, g_Hall);

    // 1) gather all inputs
    gather_x<<<Tv * Bv, 64>>>(embed, target);

    // 2) GI = X @ W_ih^T + b_ih for all steps at once: (16384,1536,K=256)
    sgemm_nt<<<dim3(H3 / 128, (Tv * Bv) / 128), 256>>>(
        pX, W_ih, b_ih, pGI, Tv * Bv, H3, Ev, 0);

    // 3) sequential recurrence: 16 x (GH gemm + gates)
    for (int t = 0; t < Tv; t++) {
        const float* hprev = (t == 0) ? context : (pHall + (size_t)(t - 1) * Bv * Hv);
        sgemm_nt<<<dim3(H3 / 128, Bv / 128), 256>>>(
            hprev, W_hh, b_hh, pGH, Bv, H3, Hv, 0);
        gru_gates<<<(Bv * Hv) / 256, 256>>>(
            pGI + (size_t)t * Bv * H3, pGH, hprev, pHall + (size_t)t * Bv * Hv);
    }

    // 4) logits for all (t,b) at once, remapped into (b,t) rows of d_out
    sgemm_nt<<<dim3((Vv + 127) / 128, (Tv * Bv) / 128), 256>>>(
        pHall, out_W, out_b, out, Tv * Bv, Vv, Hv, 1);

    // 5) in-place log-softmax per (b,t) row
    logsoftmax_rows<<<Bv * Tv, 256>>>(out);
}

// round 3
// speedup vs baseline: 2.6941x; 2.6941x over previous
#include <cuda_runtime.h>
#include <math.h>
#include <stdint.h>

#define Bv 1024
#define Tv 16
#define Vv 8000
#define Ev 256
#define Hv 512
#define H3 1536

// ---------------- scratch (static device globals) ----------------------------
__device__ float g_X[Tv * Bv * Ev];            // gathered inputs       16 MB
__device__ float g_GI[(size_t)Tv * Bv * H3];   // permuted input gates  96 MB
__device__ float g_Hall[Tv * Bv * Hv];         // hidden states         32 MB
__device__ float g_Wih_p[H3 * Ev];             // permuted W_ih        1.5 MB
__device__ float g_Whh_p[H3 * Hv];             // permuted W_hh          3 MB
__device__ float g_bih_p[H3];
__device__ float g_bhh_p[H3];

// ---------------- helpers ------------------------------------------------------
__device__ __forceinline__ uint32_t smem_u32(const void* p) {
    uint32_t a;
    asm("{ .reg .u64 t; cvta.to.shared.u64 t, %1; cvt.u32.u64 %0, t; }"
        : "=r"(a) : "l"(p));
    return a;
}
__device__ __forceinline__ uint32_t f2tf32(float x) {
    uint32_t r;
    asm("cvt.rna.tf32.f32 %0, %1;" : "=r"(r) : "f"(x));
    return r;
}
__device__ __forceinline__ void cp_async16(uint32_t dst, const void* src, uint32_t sz) {
    asm volatile("cp.async.cg.shared.global [%0], [%1], 16, %2;"
                 :: "r"(dst), "l"(src), "r"(sz) : "memory");
}
__device__ __forceinline__ void cp_commit() {
    asm volatile("cp.async.commit_group;" ::: "memory");
}
__device__ __forceinline__ void cp_wait1() {
    asm volatile("cp.async.wait_group 1;" ::: "memory");
}
__device__ __forceinline__ void mma_tf32(float* c, const uint32_t* a, const uint32_t* b) {
    asm volatile(
        "mma.sync.aligned.m16n8k8.row.col.f32.tf32.tf32.f32 "
        "{%0,%1,%2,%3}, {%4,%5,%6,%7}, {%8,%9}, {%0,%1,%2,%3};"
        : "+f"(c[0]), "+f"(c[1]), "+f"(c[2]), "+f"(c[3])
        : "r"(a[0]), "r"(a[1]), "r"(a[2]), "r"(a[3]), "r"(b[0]), "r"(b[1]));
}
__device__ __forceinline__ float sigm(float x) { return 1.f / (1.f + expf(-x)); }

// ---------------- tensor-core tf32 GEMM (mma.sync, cp.async, 3 stages) --------
// C[m,n] = sum_k A[m,k] * W[n,k]   (A: MxK row-major, W: NxK row-major)
// MODE 0: C = acc + bias                (GI)
// MODE 1: MODE 0 + row remap (t*B+b)->(b*T+t)   (logits)
// MODE 2: fused GRU gates (BN=96), writes hout  (recurrence)
template <int BN, int MODE>
__global__ void __launch_bounds__(256)
tc_gemm(const float* __restrict__ A, const float* __restrict__ W,
        const float* __restrict__ bias, float* __restrict__ C,
        int M, int N, int K,
        const float* __restrict__ gi, float* __restrict__ hout,
        const float* __restrict__ bhh) {
    constexpr int BM = 128, BK = 32, STAGES = 3;
    constexpr int LSTR = 36;                       // smem row stride (floats)
    constexpr int AFLOATS = BM * LSTR;             // per stage
    constexpr int BFLOATS = BN * LSTR;
    constexpr int NT = BN / 32;                    // n8-tiles per warp
    constexpr int WN = BN / 4;                     // warp tile width
    constexpr int BLOADS = BN * 8 / 256;           // B float4 per thread per stage

    extern __shared__ char smem[];
    float* As = (float*)smem;
    float* Bs = (float*)(smem + (size_t)STAGES * AFLOATS * 4);
    const uint32_t sA = smem_u32(smem);
    const uint32_t sB = sA + STAGES * AFLOATS * 4;

    const int tid = threadIdx.x;
    const int wid = tid >> 5, lane = tid & 31;
    const int grp = lane >> 2, tig = lane & 3;
    const int warpRow = wid >> 2, warpCol = wid & 3;
    const int mBase = blockIdx.y * BM;
    const int nBase = blockIdx.x * BN;

    // -------- stage loader ----------
    auto load_stage = [&](int s, int kc) {
        const int k0 = kc * BK;
#pragma unroll
        for (int i = 0; i < 4; i++) {              // A: 1024 float4
            int idx = i * 256 + tid;
            int row = idx >> 3, c4 = idx & 7;
            const float* src = A + (size_t)(mBase + row) * K + k0 + c4 * 4;
            cp_async16(sA + s * AFLOATS * 4 + (row * LSTR + c4 * 4) * 4, src, 16);
        }
#pragma unroll
        for (int i = 0; i < BLOADS; i++) {         // B
            int idx = i * 256 + tid;
            int row = idx >> 3, c4 = idx & 7;
            int grow = nBase + row;
            uint32_t ok = (grow < N) ? 16u : 0u;
            if (grow >= N) grow = 0;
            const float* src = W + (size_t)grow * K + k0 + c4 * 4;
            cp_async16(sB + s * BFLOATS * 4 + (row * LSTR + c4 * 4) * 4, src, ok);
        }
    };

    float acc[4][NT][4];
#pragma unroll
    for (int mt = 0; mt < 4; mt++)
#pragma unroll
        for (int nt = 0; nt < NT; nt++)
#pragma unroll
            for (int j = 0; j < 4; j++) acc[mt][nt][j] = 0.f;

    const int nk = K >> 5;
    load_stage(0, 0); cp_commit();
    load_stage(1, 1); cp_commit();

    for (int k = 0; k < nk; k++) {
        const int s = k % STAGES;
        cp_wait1();
        __syncthreads();
        if (k + 2 < nk) load_stage((k + 2) % STAGES, k + 2);
        cp_commit();

        const float* Asp = As + s * AFLOATS;
        const float* Bsp = Bs + s * BFLOATS;
#pragma unroll
        for (int kk = 0; kk < 4; kk++) {
            const int kc = kk * 8;
            uint32_t a[4][4];
#pragma unroll
            for (int mt = 0; mt < 4; mt++) {
                const int r0 = warpRow * 64 + mt * 16;
                a[mt][0] = f2tf32(Asp[(r0 + grp) * LSTR + kc + tig]);
                a[mt][1] = f2tf32(Asp[(r0 + 8 + grp) * LSTR + kc + tig]);
                a[mt][2] = f2tf32(Asp[(r0 + grp) * LSTR + kc + tig + 4]);
                a[mt][3] = f2tf32(Asp[(r0 + 8 + grp) * LSTR + kc + tig + 4]);
            }
            uint32_t b[NT][2];
#pragma unroll
            for (int nt = 0; nt < NT; nt++) {
                const int n0 = warpCol * WN + nt * 8 + grp;
                b[nt][0] = f2tf32(Bsp[n0 * LSTR + kc + tig]);
                b[nt][1] = f2tf32(Bsp[n0 * LSTR + kc + tig + 4]);
            }
#pragma unroll
            for (int mt = 0; mt < 4; mt++)
#pragma unroll
                for (int nt = 0; nt < NT; nt++)
                    mma_tf32(acc[mt][nt], a[mt], b[nt]);
        }
    }

    // -------------------- epilogue --------------------
    if constexpr (MODE != 2) {
#pragma unroll
        for (int mt = 0; mt < 4; mt++) {
            const int m0 = mBase + warpRow * 64 + mt * 16 + grp;
            const int m1 = m0 + 8;
            const int r0 = (MODE == 1) ? ((m0 & (Bv - 1)) * Tv + (m0 >> 10)) : m0;
            const int r1 = (MODE == 1) ? ((m1 & (Bv - 1)) * Tv + (m1 >> 10)) : m1;
            float* c0 = C + (size_t)r0 * N;
            float* c1 = C + (size_t)r1 * N;
#pragma unroll
            for (int nt = 0; nt < NT; nt++) {
                const int n = nBase + warpCol * WN + nt * 8 + tig * 2;
                if (n < N) {
                    float2 bv = *(const float2*)(bias + n);
                    float2 v0 = make_float2(acc[mt][nt][0] + bv.x, acc[mt][nt][1] + bv.y);
                    float2 v1 = make_float2(acc[mt][nt][2] + bv.x, acc[mt][nt][3] + bv.y);
                    *(float2*)(c0 + n) = v0;
                    *(float2*)(c1 + n) = v1;
                }
            }
        }
    } else {
        // stage GH tile to smem (reuse pipeline smem), stride 100 floats
        constexpr int GSTR = 100;
        float* gh = (float*)smem;
        __syncthreads();   // all warps done reading stage smem
#pragma unroll
        for (int mt = 0; mt < 4; mt++) {
            const int r0 = warpRow * 64 + mt * 16 + grp;
#pragma unroll
            for (int nt = 0; nt < NT; nt++) {
                const int n = warpCol * WN + nt * 8 + tig * 2;
                gh[r0 * GSTR + n] = acc[mt][nt][0];
                gh[r0 * GSTR + n + 1] = acc[mt][nt][1];
                gh[(r0 + 8) * GSTR + n] = acc[mt][nt][2];
                gh[(r0 + 8) * GSTR + n + 1] = acc[mt][nt][3];
            }
        }
        __syncthreads();
        // gate math: 128 rows x 32 q per block; layout [r32 | z32 | n32]
        const int qBase = nBase / 3;          // nBase = bx*96 -> q base = bx*32
#pragma unroll
        for (int i = 0; i < 16; i++) {
            const int idx = i * 256 + tid;    // 0..4095
            const int row = idx >> 5;
            const int q = idx & 31;
            const int m = mBase + row;
            const float ghr = gh[row * GSTR + q] + bhh[nBase + q];
            const float ghz = gh[row * GSTR + 32 + q] + bhh[nBase + 32 + q];
            const float ghn = gh[row * GSTR + 64 + q] + bhh[nBase + 64 + q];
            const float* girow = gi + (size_t)m * H3 + nBase;
            const float r = sigm(girow[q] + ghr);
            const float z = sigm(girow[32 + q] + ghz);
            const float n = tanhf(girow[64 + q] + r * ghn);
            const int qg = qBase + q;
            const float hp = A[(size_t)m * Hv + qg];   // A == hprev
            hout[(size_t)m * Hv + qg] = (1.f - z) * n + z * hp;
        }
    }
}

// ---------------- gather: xs[t] = embed[SOS or target[:, t-1]] ----------------
__global__ void gather_x(const float* __restrict__ embed,
                         const int* __restrict__ target) {
    int row = blockIdx.x;              // row = t*B + b
    int t = row >> 10;
    int b = row & (Bv - 1);
    int idx = (t == 0) ? 0 : target[b * Tv + (t - 1)];
    const float4* src = (const float4*)(embed + (size_t)idx * Ev);
    float4* dst = (float4*)(g_X + (size_t)row * Ev);
    dst[threadIdx.x] = src[threadIdx.x];
}

// ---------------- gate permutation: blocks of 96 = [r32 | z32 | n32] ----------
__global__ void permute_w(const float* __restrict__ Wih, const float* __restrict__ Whh,
                          const float* __restrict__ bih, const float* __restrict__ bhh) {
    int p = blockIdx.x;                // 0..1535
    int T = p / 96, local = p - T * 96;
    int gate = local / 32, q = T * 32 + (local - gate * 32);
    int src = gate * Hv + q;
    int t = threadIdx.x;               // 128 threads
    const float4* s1 = (const float4*)(Wih + (size_t)src * Ev);
    float4* d1 = (float4*)(g_Wih_p + (size_t)p * Ev);
    const float4* s2 = (const float4*)(Whh + (size_t)src * Hv);
    float4* d2 = (float4*)(g_Whh_p + (size_t)p * Hv);
    if (t < 64) d1[t] = s1[t];
    d2[t] = s2[t];
    if (t == 0) { g_bih_p[p] = bih[src]; g_bhh_p[p] = bhh[src]; }
}

// ---------------- in-place online log-softmax over rows of V ------------------
__global__ void __launch_bounds__(256)
logsoftmax_rows(float* __restrict__ out) {
    __shared__ float sm[256], ss[256];
    const int tid = threadIdx.x;
    float* p = out + (size_t)blockIdx.x * Vv;

    float m = -INFINITY, s = 0.f;
    for (int i = tid; i < Vv; i += 256) {
        float x = p[i];
        if (x > m) { s = s * expf(m - x) + 1.f; m = x; }
        else       { s += expf(x - m); }
    }
    sm[tid] = m; ss[tid] = s;
    __syncthreads();
    for (int st = 128; st > 0; st >>= 1) {
        if (tid < st) {
            float m2 = sm[tid + st], s2 = ss[tid + st];
            float M = fmaxf(sm[tid], m2);
            ss[tid] = ss[tid] * expf(sm[tid] - M) + s2 * expf(m2 - M);
            sm[tid] = M;
        }
        __syncthreads();
    }
    const float lse = sm[0] + logf(ss[0]);
    for (int i = tid; i < Vv; i += 256) p[i] -= lse;
}

// ---------------- launch -------------------------------------------------------
extern "C" void kernel_launch(void* const* d_in, const int* in_sizes, int n_in,
                              void* d_out, int out_size) {
    const float* context = (const float*)d_in[0];
    const int*   target  = (const int*)  d_in[1];
    const float* embed   = (const float*)d_in[2];
    const float* W_ih    = (const float*)d_in[3];
    const float* W_hh    = (const float*)d_in[4];
    const float* b_ih    = (const float*)d_in[5];
    const float* b_hh    = (const float*)d_in[6];
    const float* out_W   = (const float*)d_in[7];
    const float* out_b   = (const float*)d_in[8];
    float* out = (float*)d_out;

    float *pX, *pGI, *pHall, *pWih, *pWhh, *pbih, *pbhh;
    cudaGetSymbolAddress((void**)&pX, g_X);
    cudaGetSymbolAddress((void**)&pGI, g_GI);
    cudaGetSymbolAddress((void**)&pHall, g_Hall);
    cudaGetSymbolAddress((void**)&pWih, g_Wih_p);
    cudaGetSymbolAddress((void**)&pWhh, g_Whh_p);
    cudaGetSymbolAddress((void**)&pbih, g_bih_p);
    cudaGetSymbolAddress((void**)&pbhh, g_bhh_p);

    // dynamic smem: 3 stages * (128 + BN) * 36 floats
    const int SMEM128 = 3 * (128 + 128) * 36 * 4;   // 110592
    const int SMEM96  = 3 * (128 + 96)  * 36 * 4;   //  96768
    cudaFuncSetAttribute(tc_gemm<128, 0>,
                         cudaFuncAttributeMaxDynamicSharedMemorySize, SMEM128);
    cudaFuncSetAttribute(tc_gemm<128, 1>,
                         cudaFuncAttributeMaxDynamicSharedMemorySize, SMEM128);
    cudaFuncSetAttribute(tc_gemm<96, 2>,
                         cudaFuncAttributeMaxDynamicSharedMemorySize, SMEM96);

    // 0) permute gate weights; 1) gather inputs
    permute_w<<<H3, 128>>>(W_ih, W_hh, b_ih, b_hh);
    gather_x<<<Tv * Bv, 64>>>(embed, target);

    // 2) GI = X @ Wih_p^T + bih_p for all steps: (16384, 1536, K=256)
    tc_gemm<128, 0><<<dim3(H3 / 128, (Tv * Bv) / 128), 256, SMEM128>>>(
        pX, pWih, pbih, pGI, Tv * Bv, H3, Ev, nullptr, nullptr, nullptr);

    // 3) recurrence: fused GEMM+gates per step (grid 16 x 8 = 128 CTAs)
    for (int t = 0; t < Tv; t++) {
        const float* hprev = (t == 0) ? context : (pHall + (size_t)(t - 1) * Bv * Hv);
        tc_gemm<96, 2><<<dim3(H3 / 96, Bv / 128), 256, SMEM96>>>(
            hprev, pWhh, nullptr, nullptr, Bv, H3, Hv,
            pGI + (size_t)t * Bv * H3, pHall + (size_t)t * Bv * Hv, pbhh);
    }

    // 4) logits for all (t,b), remapped into (b,t) rows of d_out
    tc_gemm<128, 1><<<dim3((Vv + 127) / 128, (Tv * Bv) / 128), 256, SMEM128>>>(
        pHall, out_W, out_b, out, Tv * Bv, Vv, Hv, nullptr, nullptr, nullptr);

    // 5) in-place online log-softmax per (b,t) row
    logsoftmax_rows<<<Bv * Tv, 256>>>(out);
}

// round 4
// speedup vs baseline: 4.2982x; 1.5954x over previous
#include <cuda_runtime.h>
#include <cuda_bf16.h>
#include <math.h>
#include <stdint.h>

#define Bv 1024
#define Tv 16
#define Vv 8000
#define Ev 256
#define Hv 512
#define H3 1536

// ---------------- scratch (static device globals) ----------------------------
__device__ __nv_bfloat16 g_Xb[Tv * Bv * Ev];          // gathered inputs (bf16)  8 MB
__device__ float g_GI[(size_t)Tv * Bv * H3];          // permuted input gates   96 MB
__device__ float g_Hall[Tv * Bv * Hv];                // hidden states (fp32)   32 MB
__device__ __nv_bfloat16 g_Hbf[Tv * Bv * Hv];         // hidden states (bf16)   16 MB
__device__ __nv_bfloat16 g_Wih_b[H3 * Ev];            // permuted W_ih (bf16)
__device__ float g_Whh_p[H3 * Hv];                    // permuted W_hh (fp32)
__device__ __nv_bfloat16 g_Wout_b[Vv * Hv];           // out_W (bf16)            8 MB
__device__ float g_bih_p[H3];
__device__ float g_bhh_p[H3];

// ---------------- helpers ------------------------------------------------------
__device__ __forceinline__ uint32_t smem_u32(const void* p) {
    uint32_t a;
    asm("{ .reg .u64 t; cvta.to.shared.u64 t, %1; cvt.u32.u64 %0, t; }"
        : "=r"(a) : "l"(p));
    return a;
}
__device__ __forceinline__ uint32_t f2bf2(float lo, float hi) {
    uint32_t r;
    asm("cvt.rn.bf16x2.f32 %0, %1, %2;" : "=r"(r) : "f"(hi), "f"(lo));
    return r;
}
__device__ __forceinline__ void cp_async16(uint32_t dst, const void* src, uint32_t sz) {
    asm volatile("cp.async.cg.shared.global [%0], [%1], 16, %2;"
                 :: "r"(dst), "l"(src), "r"(sz) : "memory");
}
__device__ __forceinline__ void cp_commit() {
    asm volatile("cp.async.commit_group;" ::: "memory");
}
__device__ __forceinline__ void cp_wait1() {
    asm volatile("cp.async.wait_group 1;" ::: "memory");
}
__device__ __forceinline__ void cp_wait_all() {
    asm volatile("cp.async.wait_all;" ::: "memory");
}
__device__ __forceinline__ void mma_tf32(float* c, const uint32_t* a, const uint32_t* b) {
    asm volatile(
        "mma.sync.aligned.m16n8k8.row.col.f32.tf32.tf32.f32 "
        "{%0,%1,%2,%3}, {%4,%5,%6,%7}, {%8,%9}, {%0,%1,%2,%3};"
        : "+f"(c[0]), "+f"(c[1]), "+f"(c[2]), "+f"(c[3])
        : "r"(a[0]), "r"(a[1]), "r"(a[2]), "r"(a[3]), "r"(b[0]), "r"(b[1]));
}
__device__ __forceinline__ void mma_bf16(float* c, const uint32_t* a, const uint32_t* b) {
    asm volatile(
        "mma.sync.aligned.m16n8k16.row.col.f32.bf16.bf16.f32 "
        "{%0,%1,%2,%3}, {%4,%5,%6,%7}, {%8,%9}, {%0,%1,%2,%3};"
        : "+f"(c[0]), "+f"(c[1]), "+f"(c[2]), "+f"(c[3])
        : "r"(a[0]), "r"(a[1]), "r"(a[2]), "r"(a[3]), "r"(b[0]), "r"(b[1]));
}
__device__ __forceinline__ float sigm(float x) { return 1.f / (1.f + expf(-x)); }

// ================== bf16 GEMM (m16n8k16, cp.async 3-stage) =====================
// C[m,n] = sum_k A[m,k] * W[n,k] + bias[n]    (A: MxK bf16, W: NxK bf16)
// MODE 0: plain (GI).  MODE 1: row remap (t*B+b)->(b*T+t) (logits).
template <int BN, int MODE>
__global__ void __launch_bounds__(256)
bf_gemm(const __nv_bfloat16* __restrict__ A, const __nv_bfloat16* __restrict__ W,
        const float* __restrict__ bias, float* __restrict__ C,
        int M, int N, int K) {
    constexpr int BM = 128, STAGES = 3;
    constexpr int RSTR = 20;                 // u32 per smem row (16 data + 4 pad)
    constexpr int ASTG = BM * RSTR;          // u32 per stage
    constexpr int BSTG = BN * RSTR;
    constexpr int NT = BN / 32;
    constexpr int WN = BN / 4;

    extern __shared__ uint32_t smu[];
    uint32_t* As = smu;
    uint32_t* Bs = smu + STAGES * ASTG;
    const uint32_t sA = smem_u32(smu);
    const uint32_t sB = sA + STAGES * ASTG * 4;

    const int tid = threadIdx.x;
    const int wid = tid >> 5, lane = tid & 31;
    const int grp = lane >> 2, tig = lane & 3;
    const int warpRow = wid >> 2, warpCol = wid & 3;
    const int mBase = blockIdx.y * BM;
    const int nBase = blockIdx.x * BN;

    auto load_stage = [&](int s, int kc) {
        const int k0 = kc * 32;
#pragma unroll
        for (int i = 0; i < 2; i++) {                   // A: 512 x 16B
            int idx = i * 256 + tid;
            int row = idx >> 2, c = idx & 3;
            const void* src = A + (size_t)(mBase + row) * K + k0 + c * 8;
            cp_async16(sA + (s * ASTG + row * RSTR + c * 4) * 4, src, 16);
        }
#pragma unroll
        for (int i = 0; i < BN / 64; i++) {             // B: BN*4 x 16B
            int idx = i * 256 + tid;
            int row = idx >> 2, c = idx & 3;
            int g = nBase + row;
            uint32_t ok = (g < N) ? 16u : 0u;
            if (g >= N) g = 0;
            cp_async16(sB + (s * BSTG + row * RSTR + c * 4) * 4,
                       W + (size_t)g * K + k0 + c * 8, ok);
        }
    };

    float acc[4][NT][4];
#pragma unroll
    for (int mt = 0; mt < 4; mt++)
#pragma unroll
        for (int nt = 0; nt < NT; nt++)
#pragma unroll
            for (int j = 0; j < 4; j++) acc[mt][nt][j] = 0.f;

    const int nk = K >> 5;
    load_stage(0, 0); cp_commit();
    load_stage(1, 1); cp_commit();

    for (int k = 0; k < nk; k++) {
        const int s = k % STAGES;
        cp_wait1();
        __syncthreads();
        if (k + 2 < nk) load_stage((k + 2) % STAGES, k + 2);
        cp_commit();

        const uint32_t* Asp = As + s * ASTG;
        const uint32_t* Bsp = Bs + s * BSTG;
#pragma unroll
        for (int kk = 0; kk < 2; kk++) {                // two k16 halves
            const int kc = kk * 8;
            uint32_t a[4][4];
#pragma unroll
            for (int mt = 0; mt < 4; mt++) {
                const int r0 = warpRow * 64 + mt * 16;
                a[mt][0] = Asp[(r0 + grp) * RSTR + kc + tig];
                a[mt][1] = Asp[(r0 + 8 + grp) * RSTR + kc + tig];
                a[mt][2] = Asp[(r0 + grp) * RSTR + kc + tig + 4];
                a[mt][3] = Asp[(r0 + 8 + grp) * RSTR + kc + tig + 4];
            }
            uint32_t b[NT][2];
#pragma unroll
            for (int nt = 0; nt < NT; nt++) {
                const int n0 = warpCol * WN + nt * 8 + grp;
                b[nt][0] = Bsp[n0 * RSTR + kc + tig];
                b[nt][1] = Bsp[n0 * RSTR + kc + tig + 4];
            }
#pragma unroll
            for (int mt = 0; mt < 4; mt++)
#pragma unroll
                for (int nt = 0; nt < NT; nt++)
                    mma_bf16(acc[mt][nt], a[mt], b[nt]);
        }
    }

    // epilogue: bias + store (optional row remap)
#pragma unroll
    for (int mt = 0; mt < 4; mt++) {
        const int m0 = mBase + warpRow * 64 + mt * 16 + grp;
        const int m1 = m0 + 8;
        const int r0 = (MODE == 1) ? ((m0 & (Bv - 1)) * Tv + (m0 >> 10)) : m0;
        const int r1 = (MODE == 1) ? ((m1 & (Bv - 1)) * Tv + (m1 >> 10)) : m1;
        float* c0 = C + (size_t)r0 * N;
        float* c1 = C + (size_t)r1 * N;
#pragma unroll
        for (int nt = 0; nt < NT; nt++) {
            const int n = nBase + warpCol * WN + nt * 8 + tig * 2;
            if (n < N) {
                float2 bv = *(const float2*)(bias + n);
                *(float2*)(c0 + n) = make_float2(acc[mt][nt][0] + bv.x,
                                                 acc[mt][nt][1] + bv.y);
                *(float2*)(c1 + n) = make_float2(acc[mt][nt][2] + bv.x,
                                                 acc[mt][nt][3] + bv.y);
            }
        }
    }
}

// ================== tf32 recurrence GEMM + fused GRU gates =====================
// BM=64, BN=96 ([r32|z32|n32] blocks). A = hprev (fp32), W = Whh_p (fp32).
__global__ void __launch_bounds__(256)
tc_rec(const float* __restrict__ A, const float* __restrict__ W,
       const float* __restrict__ gi, float* __restrict__ hout,
       __nv_bfloat16* __restrict__ hbf, const float* __restrict__ bhh) {
    constexpr int BM = 64, BN = 96, STAGES = 3, LSTR = 36;
    constexpr int AFLOATS = BM * LSTR, BFLOATS = BN * LSTR;
    constexpr int K = Hv, NT = 3, WN = 24;

    extern __shared__ uint32_t smu[];
    float* As = (float*)smu;
    float* Bs = As + STAGES * AFLOATS;
    const uint32_t sA = smem_u32(smu);
    const uint32_t sB = sA + STAGES * AFLOATS * 4;

    const int tid = threadIdx.x;
    const int wid = tid >> 5, lane = tid & 31;
    const int grp = lane >> 2, tig = lane & 3;
    const int warpRow = wid >> 2, warpCol = wid & 3;
    const int mBase = blockIdx.y * BM;
    const int nBase = blockIdx.x * BN;

    auto load_stage = [&](int s, int kc) {
        const int k0 = kc * 32;
#pragma unroll
        for (int i = 0; i < 2; i++) {                   // A: 512 float4
            int idx = i * 256 + tid;
            int row = idx >> 3, c4 = idx & 7;
            cp_async16(sA + (s * AFLOATS + row * LSTR + c4 * 4) * 4,
                       A + (size_t)(mBase + row) * K + k0 + c4 * 4, 16);
        }
#pragma unroll
        for (int i = 0; i < 3; i++) {                   // B: 768 float4
            int idx = i * 256 + tid;
            int row = idx >> 3, c4 = idx & 7;
            cp_async16(sB + (s * BFLOATS + row * LSTR + c4 * 4) * 4,
                       W + (size_t)(nBase + row) * K + k0 + c4 * 4, 16);
        }
    };

    float acc[2][NT][4];
#pragma unroll
    for (int mt = 0; mt < 2; mt++)
#pragma unroll
        for (int nt = 0; nt < NT; nt++)
#pragma unroll
            for (int j = 0; j < 4; j++) acc[mt][nt][j] = 0.f;

    const int nk = K >> 5;
    load_stage(0, 0); cp_commit();
    load_stage(1, 1); cp_commit();

    for (int k = 0; k < nk; k++) {
        const int s = k % STAGES;
        cp_wait1();
        __syncthreads();
        if (k + 2 < nk) load_stage((k + 2) % STAGES, k + 2);
        cp_commit();

        const uint32_t* Asp = (const uint32_t*)(As + s * AFLOATS);
        const uint32_t* Bsp = (const uint32_t*)(Bs + s * BFLOATS);
#pragma unroll
        for (int kk = 0; kk < 4; kk++) {
            const int kc = kk * 8;
            uint32_t a[2][4];
#pragma unroll
            for (int mt = 0; mt < 2; mt++) {
                const int r0 = warpRow * 32 + mt * 16;
                a[mt][0] = Asp[(r0 + grp) * LSTR + kc + tig];
                a[mt][1] = Asp[(r0 + 8 + grp) * LSTR + kc + tig];
                a[mt][2] = Asp[(r0 + grp) * LSTR + kc + tig + 4];
                a[mt][3] = Asp[(r0 + 8 + grp) * LSTR + kc + tig + 4];
            }
            uint32_t b[NT][2];
#pragma unroll
            for (int nt = 0; nt < NT; nt++) {
                const int n0 = warpCol * WN + nt * 8 + grp;
                b[nt][0] = Bsp[n0 * LSTR + kc + tig];
                b[nt][1] = Bsp[n0 * LSTR + kc + tig + 4];
            }
#pragma unroll
            for (int mt = 0; mt < 2; mt++)
#pragma unroll
                for (int nt = 0; nt < NT; nt++)
                    mma_tf32(acc[mt][nt], a[mt], b[nt]);
        }
    }

    // -------- epilogue: stage GH to smem, fused gate math --------
    constexpr int GSTR = 100;
    float* gh = (float*)smu;
    cp_wait_all();
    __syncthreads();
#pragma unroll
    for (int mt = 0; mt < 2; mt++) {
        const int r0 = warpRow * 32 + mt * 16 + grp;
#pragma unroll
        for (int nt = 0; nt < NT; nt++) {
            const int n = warpCol * WN + nt * 8 + tig * 2;
            gh[r0 * GSTR + n] = acc[mt][nt][0];
            gh[r0 * GSTR + n + 1] = acc[mt][nt][1];
            gh[(r0 + 8) * GSTR + n] = acc[mt][nt][2];
            gh[(r0 + 8) * GSTR + n + 1] = acc[mt][nt][3];
        }
    }
    __syncthreads();
    const int qBase = nBase / 3;          // nBase = bx*96 -> q base = bx*32
#pragma unroll
    for (int i = 0; i < 8; i++) {
        const int idx = i * 256 + tid;    // 0..2047
        const int row = idx >> 5;
        const int q = idx & 31;
        const int m = mBase + row;
        const float ghr = gh[row * GSTR + q] + bhh[nBase + q];
        const float ghz = gh[row * GSTR + 32 + q] + bhh[nBase + 32 + q];
        const float ghn = gh[row * GSTR + 64 + q] + bhh[nBase + 64 + q];
        const float* girow = gi + (size_t)m * H3 + nBase;
        const float r = sigm(girow[q] + ghr);
        const float z = sigm(girow[32 + q] + ghz);
        const float n = tanhf(girow[64 + q] + r * ghn);
        const int qg = qBase + q;
        const float hp = A[(size_t)m * Hv + qg];
        const float h = (1.f - z) * n + z * hp;
        hout[(size_t)m * Hv + qg] = h;
        hbf[(size_t)m * Hv + qg] = __float2bfloat16(h);
    }
}

// ---------------- prep kernels -------------------------------------------------
__global__ void gather_x(const float* __restrict__ embed,
                         const int* __restrict__ target) {
    int row = blockIdx.x;              // row = t*B + b
    int t = row >> 10;
    int b = row & (Bv - 1);
    int idx = (t == 0) ? 0 : target[b * Tv + (t - 1)];
    float4 v = ((const float4*)(embed + (size_t)idx * Ev))[threadIdx.x];
    uint2 o = make_uint2(f2bf2(v.x, v.y), f2bf2(v.z, v.w));
    ((uint2*)(g_Xb + (size_t)row * Ev))[threadIdx.x] = o;
}

__global__ void permute_w(const float* __restrict__ Wih, const float* __restrict__ Whh,
                          const float* __restrict__ bih, const float* __restrict__ bhh) {
    int p = blockIdx.x;                // 0..1535
    int T = p / 96, local = p - T * 96;
    int gate = local / 32, q = T * 32 + (local - gate * 32);
    int src = gate * Hv + q;
    int t = threadIdx.x;               // 128 threads
    if (t < 64) {
        float4 v = ((const float4*)(Wih + (size_t)src * Ev))[t];
        uint2 o = make_uint2(f2bf2(v.x, v.y), f2bf2(v.z, v.w));
        ((uint2*)(g_Wih_b + (size_t)p * Ev))[t] = o;
    }
    ((float4*)(g_Whh_p + (size_t)p * Hv))[t] =
        ((const float4*)(Whh + (size_t)src * Hv))[t];
    if (t == 0) { g_bih_p[p] = bih[src]; g_bhh_p[p] = bhh[src]; }
}

__global__ void conv_outw(const float* __restrict__ W) {
    size_t i = ((size_t)blockIdx.x * 256 + threadIdx.x) * 4;
    float4 v = *(const float4*)(W + i);
    uint2 o = make_uint2(f2bf2(v.x, v.y), f2bf2(v.z, v.w));
    *(uint2*)(g_Wout_b + i) = o;
}

// ---------------- log-softmax with smem row cache ------------------------------
__global__ void __launch_bounds__(256)
logsoftmax_rows(float* __restrict__ out) {
    extern __shared__ float rowc[];     // Vv floats
    __shared__ float sm[256], ss[256];
    const int tid = threadIdx.x;
    float* p = out + (size_t)blockIdx.x * Vv;

    float m = -INFINITY, s = 0.f;
    for (int i = tid; i < Vv; i += 256) {
        float x = p[i];
        rowc[i] = x;
        if (x > m) { s = s * expf(m - x) + 1.f; m = x; }
        else       { s += expf(x - m); }
    }
    sm[tid] = m; ss[tid] = s;
    __syncthreads();
    for (int st = 128; st > 0; st >>= 1) {
        if (tid < st) {
            float m2 = sm[tid + st], s2 = ss[tid + st];
            float M = fmaxf(sm[tid], m2);
            ss[tid] = ss[tid] * expf(sm[tid] - M) + s2 * expf(m2 - M);
            sm[tid] = M;
        }
        __syncthreads();
    }
    const float lse = sm[0] + logf(ss[0]);
    for (int i = tid; i < Vv; i += 256) p[i] = rowc[i] - lse;
}

// ---------------- launch --------------------------------------------------------
extern "C" void kernel_launch(void* const* d_in, const int* in_sizes, int n_in,
                              void* d_out, int out_size) {
    const float* context = (const float*)d_in[0];
    const int*   target  = (const int*)  d_in[1];
    const float* embed   = (const float*)d_in[2];
    const float* W_ih    = (const float*)d_in[3];
    const float* W_hh    = (const float*)d_in[4];
    const float* b_ih    = (const float*)d_in[5];
    const float* b_hh    = (const float*)d_in[6];
    const float* out_W   = (const float*)d_in[7];
    const float* out_b   = (const float*)d_in[8];
    float* out = (float*)d_out;

    float *pGI, *pHall, *pWhh, *pbih, *pbhh;
    __nv_bfloat16 *pXb, *pHbf, *pWihb, *pWoutb;
    cudaGetSymbolAddress((void**)&pXb, g_Xb);
    cudaGetSymbolAddress((void**)&pGI, g_GI);
    cudaGetSymbolAddress((void**)&pHall, g_Hall);
    cudaGetSymbolAddress((void**)&pHbf, g_Hbf);
    cudaGetSymbolAddress((void**)&pWihb, g_Wih_b);
    cudaGetSymbolAddress((void**)&pWhh, g_Whh_p);
    cudaGetSymbolAddress((void**)&pWoutb, g_Wout_b);
    cudaGetSymbolAddress((void**)&pbih, g_bih_p);
    cudaGetSymbolAddress((void**)&pbhh, g_bhh_p);

    const int SMEMBF  = 3 * (128 + 128) * 20 * 4;   // 61440
    const int SMEMREC = 3 * (64 + 96) * 36 * 4;     // 69120
    const int SMEMSFT = Vv * 4;                      // 32000
    cudaFuncSetAttribute(bf_gemm<128, 0>,
                         cudaFuncAttributeMaxDynamicSharedMemorySize, SMEMBF);
    cudaFuncSetAttribute(bf_gemm<128, 1>,
                         cudaFuncAttributeMaxDynamicSharedMemorySize, SMEMBF);
    cudaFuncSetAttribute(tc_rec,
                         cudaFuncAttributeMaxDynamicSharedMemorySize, SMEMREC);
    cudaFuncSetAttribute(logsoftmax_rows,
                         cudaFuncAttributeMaxDynamicSharedMemorySize, SMEMSFT);

    // 0) prep: permute/convert weights, gather+convert inputs
    permute_w<<<H3, 128>>>(W_ih, W_hh, b_ih, b_hh);
    conv_outw<<<(Vv * Hv) / 1024, 256>>>(out_W);
    gather_x<<<Tv * Bv, 64>>>(embed, target);

    // 1) GI = X @ Wih^T + bih (bf16 tensor cores): (16384, 1536, K=256)
    bf_gemm<128, 0><<<dim3(H3 / 128, (Tv * Bv) / 128), 256, SMEMBF>>>(
        pXb, pWihb, pbih, pGI, Tv * Bv, H3, Ev);

    // 2) recurrence: fused tf32 GEMM + gates per step (grid 16 x 16)
    for (int t = 0; t < Tv; t++) {
        const float* hprev = (t == 0) ? context : (pHall + (size_t)(t - 1) * Bv * Hv);
        tc_rec<<<dim3(H3 / 96, Bv / 64), 256, SMEMREC>>>(
            hprev, pWhh, pGI + (size_t)t * Bv * H3,
            pHall + (size_t)t * Bv * Hv, pHbf + (size_t)t * Bv * Hv, pbhh);
    }

    // 3) logits (bf16): (16384, 8000, K=512), remapped rows
    bf_gemm<128, 1><<<dim3((Vv + 127) / 128, (Tv * Bv) / 128), 256, SMEMBF>>>(
        pHbf, pWoutb, out_b, out, Tv * Bv, Vv, Hv);

    // 4) in-place log-softmax per (b,t) row
    logsoftmax_rows<<<Bv * Tv, 256, SMEMSFT>>>(out);
}

// round 5
// speedup vs baseline: 4.8372x; 1.1254x over previous
#include <cuda_runtime.h>
#include <cuda_bf16.h>
#include <math.h>
#include <stdint.h>

#define Bv 1024
#define Tv 16
#define Vv 8000
#define Ev 256
#define Hv 512
#define H3 1536

// ---------------- scratch (static device globals) ----------------------------
__device__ __nv_bfloat16 g_Xb[Tv * Bv * Ev];           // gathered inputs (bf16)
__device__ float g_GI[(size_t)Tv * Bv * H3];           // permuted input gates
__device__ float g_Hall[Tv * Bv * Hv];                 // hidden states (fp32 carry)
__device__ __nv_bfloat16 g_Hbf[(Tv + 1) * Bv * Hv];    // slice0=context, t+1=step t
__device__ __nv_bfloat16 g_Wih_b[H3 * Ev];             // permuted W_ih (bf16)
__device__ __nv_bfloat16 g_Whh_b[H3 * Hv];             // permuted W_hh (bf16)
__device__ __nv_bfloat16 g_Wout_b[Vv * Hv];            // out_W (bf16)
__device__ float g_bih_p[H3];
__device__ float g_bhh_p[H3];

// ---------------- helpers ------------------------------------------------------
__device__ __forceinline__ uint32_t smem_u32(const void* p) {
    uint32_t a;
    asm("{ .reg .u64 t; cvta.to.shared.u64 t, %1; cvt.u32.u64 %0, t; }"
        : "=r"(a) : "l"(p));
    return a;
}
__device__ __forceinline__ uint32_t f2bf2(float lo, float hi) {
    uint32_t r;
    asm("cvt.rn.bf16x2.f32 %0, %1, %2;" : "=r"(r) : "f"(hi), "f"(lo));
    return r;
}
__device__ __forceinline__ void cp_async16(uint32_t dst, const void* src, uint32_t sz) {
    asm volatile("cp.async.cg.shared.global [%0], [%1], 16, %2;"
                 :: "r"(dst), "l"(src), "r"(sz) : "memory");
}
__device__ __forceinline__ void cp_commit() {
    asm volatile("cp.async.commit_group;" ::: "memory");
}
__device__ __forceinline__ void cp_wait1() {
    asm volatile("cp.async.wait_group 1;" ::: "memory");
}
__device__ __forceinline__ void ldm_x4(uint32_t* r, uint32_t addr) {
    asm volatile("ldmatrix.sync.aligned.m8n8.x4.shared.b16 {%0,%1,%2,%3}, [%4];"
                 : "=r"(r[0]), "=r"(r[1]), "=r"(r[2]), "=r"(r[3]) : "r"(addr));
}
__device__ __forceinline__ void ldm_x2(uint32_t* r, uint32_t addr) {
    asm volatile("ldmatrix.sync.aligned.m8n8.x2.shared.b16 {%0,%1}, [%2];"
                 : "=r"(r[0]), "=r"(r[1]) : "r"(addr));
}
__device__ __forceinline__ void mma_bf16(float* c, const uint32_t* a, const uint32_t* b) {
    asm volatile(
        "mma.sync.aligned.m16n8k16.row.col.f32.bf16.bf16.f32 "
        "{%0,%1,%2,%3}, {%4,%5,%6,%7}, {%8,%9}, {%0,%1,%2,%3};"
        : "+f"(c[0]), "+f"(c[1]), "+f"(c[2]), "+f"(c[3])
        : "r"(a[0]), "r"(a[1]), "r"(a[2]), "r"(a[3]), "r"(b[0]), "r"(b[1]));
}
__device__ __forceinline__ float sigm(float x) { return 1.f / (1.f + expf(-x)); }

// ================== bf16 GEMM (ldmatrix + m16n8k16, 3-stage cp.async) ==========
// C[m,n] = sum_k A[m,k]*W[n,k] + bias[n]   (A: MxK bf16, W: NxK bf16, K%32==0)
// MODE 0: plain (GI).  MODE 1: row remap (t*B+b)->(b*T+t) (logits).
template <int MODE>
__global__ void __launch_bounds__(256)
bf_gemm(const __nv_bfloat16* __restrict__ A, const __nv_bfloat16* __restrict__ W,
        const float* __restrict__ bias, float* __restrict__ C,
        int M, int N, int K) {
    constexpr int BM = 128, BN = 128, STAGES = 3;
    constexpr int RSTR = 20;                 // u32 per smem row (16 data + 4 pad)
    constexpr int ASTG = BM * RSTR;          // u32 per stage
    constexpr int BSTG = BN * RSTR;

    extern __shared__ uint32_t smu[];
    const uint32_t sA = smem_u32(smu);
    const uint32_t sB = sA + STAGES * ASTG * 4;

    const int tid = threadIdx.x;
    const int wid = tid >> 5, lane = tid & 31;
    const int grp = lane >> 2, tig = lane & 3;
    const int warpRow = wid >> 2, warpCol = wid & 3;
    const int mBase = blockIdx.y * BM;
    const int nBase = blockIdx.x * BN;

    auto load_stage = [&](int s, int kc) {
        const int k0 = kc * 32;
#pragma unroll
        for (int i = 0; i < 2; i++) {                   // A: 512 x 16B
            int idx = i * 256 + tid;
            int row = idx >> 2, c = idx & 3;
            cp_async16(sA + (s * ASTG + row * RSTR + c * 4) * 4,
                       A + (size_t)(mBase + row) * K + k0 + c * 8, 16);
        }
#pragma unroll
        for (int i = 0; i < 2; i++) {                   // B: 512 x 16B
            int idx = i * 256 + tid;
            int row = idx >> 2, c = idx & 3;
            int g = nBase + row;
            uint32_t ok = (g < N) ? 16u : 0u;
            if (g >= N) g = 0;
            cp_async16(sB + (s * BSTG + row * RSTR + c * 4) * 4,
                       W + (size_t)g * K + k0 + c * 8, 16);   // note: sz arg below
        }
    };
    // NOTE: predicate via ok applied in second loop; re-issue with ok:
    (void)load_stage;

    auto load_stage2 = [&](int s, int kc) {
        const int k0 = kc * 32;
#pragma unroll
        for (int i = 0; i < 2; i++) {
            int idx = i * 256 + tid;
            int row = idx >> 2, c = idx & 3;
            cp_async16(sA + (s * ASTG + row * RSTR + c * 4) * 4,
                       A + (size_t)(mBase + row) * K + k0 + c * 8, 16);
        }
#pragma unroll
        for (int i = 0; i < 2; i++) {
            int idx = i * 256 + tid;
            int row = idx >> 2, c = idx & 3;
            int g = nBase + row;
            uint32_t ok = (g < N) ? 16u : 0u;
            if (g >= N) g = 0;
            cp_async16(sB + (s * BSTG + row * RSTR + c * 4) * 4,
                       W + (size_t)g * K + k0 + c * 8, ok);
        }
    };

    // ldmatrix per-thread base offsets (bytes, stage-relative)
    const int a_r = lane & 15, a_c = (lane >> 4) * 4;              // A x4
    const int b_r = (lane >> 4) * 8 + (lane & 7), b_c = ((lane >> 3) & 1) * 4;
    uint32_t aOff[4], bOff[2];
#pragma unroll
    for (int mt = 0; mt < 4; mt++)
        aOff[mt] = ((warpRow * 64 + mt * 16 + a_r) * RSTR + a_c) * 4;
#pragma unroll
    for (int nb = 0; nb < 2; nb++)
        bOff[nb] = ((warpCol * 32 + nb * 16 + b_r) * RSTR + b_c) * 4;

    float acc[4][4][4];
#pragma unroll
    for (int mt = 0; mt < 4; mt++)
#pragma unroll
        for (int nt = 0; nt < 4; nt++)
#pragma unroll
            for (int j = 0; j < 4; j++) acc[mt][nt][j] = 0.f;

    const int nk = K >> 5;
    load_stage2(0, 0); cp_commit();
    load_stage2(1, 1); cp_commit();

    for (int k = 0; k < nk; k++) {
        const int s = k % STAGES;
        cp_wait1();
        __syncthreads();
        if (k + 2 < nk) load_stage2((k + 2) % STAGES, k + 2);
        cp_commit();

        const uint32_t aS = sA + s * ASTG * 4;
        const uint32_t bS = sB + s * BSTG * 4;
#pragma unroll
        for (int kk = 0; kk < 2; kk++) {                // two k16 halves (32B apart)
            uint32_t a[4][4], b[2][4];
#pragma unroll
            for (int mt = 0; mt < 4; mt++) ldm_x4(a[mt], aS + aOff[mt] + kk * 32);
#pragma unroll
            for (int nb = 0; nb < 2; nb++) ldm_x4(b[nb], bS + bOff[nb] + kk * 32);
#pragma unroll
            for (int mt = 0; mt < 4; mt++)
#pragma unroll
                for (int nt = 0; nt < 4; nt++)
                    mma_bf16(acc[mt][nt], a[mt], &b[nt >> 1][(nt & 1) * 2]);
        }
    }

    // epilogue: bias + store (optional row remap)
#pragma unroll
    for (int mt = 0; mt < 4; mt++) {
        const int m0 = mBase + warpRow * 64 + mt * 16 + grp;
        const int m1 = m0 + 8;
        const int r0 = (MODE == 1) ? ((m0 & (Bv - 1)) * Tv + (m0 >> 10)) : m0;
        const int r1 = (MODE == 1) ? ((m1 & (Bv - 1)) * Tv + (m1 >> 10)) : m1;
        float* c0 = C + (size_t)r0 * N;
        float* c1 = C + (size_t)r1 * N;
#pragma unroll
        for (int nt = 0; nt < 4; nt++) {
            const int n = nBase + warpCol * 32 + nt * 8 + tig * 2;
            if (n < N) {
                float2 bv = *(const float2*)(bias + n);
                *(float2*)(c0 + n) = make_float2(acc[mt][nt][0] + bv.x,
                                                 acc[mt][nt][1] + bv.y);
                *(float2*)(c1 + n) = make_float2(acc[mt][nt][2] + bv.x,
                                                 acc[mt][nt][3] + bv.y);
            }
        }
    }
}

// ================== bf16 recurrence GEMM + fused GRU gates =====================
// BM=64, BN=96 ([r32|z32|n32] blocks), BK=64. A = hprev bf16, W = Whh_b.
__global__ void __launch_bounds__(256)
rec_step(const __nv_bfloat16* __restrict__ A, const __nv_bfloat16* __restrict__ W,
         const float* __restrict__ gi, const float* __restrict__ hpf,
         float* __restrict__ hout, __nv_bfloat16* __restrict__ hbf,
         const float* __restrict__ bhh) {
    constexpr int STAGES = 3, RSTR = 36;     // 32 data u32 + 4 pad (BK=64 bf16)
    constexpr int ASTG = 64 * RSTR, BSTG = 96 * RSTR;
    constexpr int K = Hv;

    extern __shared__ uint32_t smu[];
    const uint32_t sA = smem_u32(smu);
    const uint32_t sB = sA + STAGES * ASTG * 4;

    const int tid = threadIdx.x;
    const int wid = tid >> 5, lane = tid & 31;
    const int grp = lane >> 2, tig = lane & 3;
    const int warpRow = wid >> 2, warpCol = wid & 3;   // 2 x 4, warp tile 32x24
    const int mBase = blockIdx.y * 64;
    const int nBase = blockIdx.x * 96;

    auto load_stage = [&](int s, int kc) {
        const int k0 = kc * 64;
#pragma unroll
        for (int i = 0; i < 2; i++) {                   // A: 512 x 16B
            int idx = i * 256 + tid;
            int row = idx >> 3, c = idx & 7;
            cp_async16(sA + (s * ASTG + row * RSTR + c * 4) * 4,
                       A + (size_t)(mBase + row) * K + k0 + c * 8, 16);
        }
#pragma unroll
        for (int i = 0; i < 3; i++) {                   // B: 768 x 16B
            int idx = i * 256 + tid;
            int row = idx >> 3, c = idx & 7;
            cp_async16(sB + (s * BSTG + row * RSTR + c * 4) * 4,
                       W + (size_t)(nBase + row) * K + k0 + c * 8, 16);
        }
    };

    const int a_r = lane & 15, a_c = (lane >> 4) * 4;
    const int b_r = (lane >> 4) * 8 + (lane & 7), b_c = ((lane >> 3) & 1) * 4;
    const int b2_r = lane & 7, b2_c = ((lane >> 3) & 1) * 4;   // x2 (lanes 0-15)
    uint32_t aOff[2], bOff, b2Off;
#pragma unroll
    for (int mt = 0; mt < 2; mt++)
        aOff[mt] = ((warpRow * 32 + mt * 16 + a_r) * RSTR + a_c) * 4;
    bOff  = ((warpCol * 24 + b_r) * RSTR + b_c) * 4;
    b2Off = ((warpCol * 24 + 16 + b2_r) * RSTR + b2_c) * 4;

    float acc[2][3][4];
#pragma unroll
    for (int mt = 0; mt < 2; mt++)
#pragma unroll
        for (int nt = 0; nt < 3; nt++)
#pragma unroll
            for (int j = 0; j < 4; j++) acc[mt][nt][j] = 0.f;

    const int nk = K >> 6;                    // 8
    load_stage(0, 0); cp_commit();
    load_stage(1, 1); cp_commit();

    for (int k = 0; k < nk; k++) {
        const int s = k % STAGES;
        cp_wait1();
        __syncthreads();
        if (k + 2 < nk) load_stage((k + 2) % STAGES, k + 2);
        cp_commit();

        const uint32_t aS = sA + s * ASTG * 4;
        const uint32_t bS = sB + s * BSTG * 4;
#pragma unroll
        for (int kk = 0; kk < 4; kk++) {
            uint32_t a[2][4], b01[4], b2[2];
#pragma unroll
            for (int mt = 0; mt < 2; mt++) ldm_x4(a[mt], aS + aOff[mt] + kk * 32);
            ldm_x4(b01, bS + bOff + kk * 32);
            ldm_x2(b2, bS + b2Off + kk * 32);
#pragma unroll
            for (int mt = 0; mt < 2; mt++) {
                mma_bf16(acc[mt][0], a[mt], &b01[0]);
                mma_bf16(acc[mt][1], a[mt], &b01[2]);
                mma_bf16(acc[mt][2], a[mt], b2);
            }
        }
    }

    // -------- epilogue: stage GH to smem, fused gate math --------
    constexpr int GSTR = 100;
    float* gh = (float*)smu;
    asm volatile("cp.async.wait_all;" ::: "memory");
    __syncthreads();
#pragma unroll
    for (int mt = 0; mt < 2; mt++) {
        const int r0 = warpRow * 32 + mt * 16 + grp;
#pragma unroll
        for (int nt = 0; nt < 3; nt++) {
            const int n = warpCol * 24 + nt * 8 + tig * 2;
            gh[r0 * GSTR + n] = acc[mt][nt][0];
            gh[r0 * GSTR + n + 1] = acc[mt][nt][1];
            gh[(r0 + 8) * GSTR + n] = acc[mt][nt][2];
            gh[(r0 + 8) * GSTR + n + 1] = acc[mt][nt][3];
        }
    }
    __syncthreads();
    const int qBase = nBase / 3;              // nBase = bx*96 -> q base = bx*32
#pragma unroll
    for (int i = 0; i < 8; i++) {
        const int idx = i * 256 + tid;        // 0..2047
        const int row = idx >> 5;
        const int q = idx & 31;
        const int m = mBase + row;
        const float ghr = gh[row * GSTR + q] + bhh[nBase + q];
        const float ghz = gh[row * GSTR + 32 + q] + bhh[nBase + 32 + q];
        const float ghn = gh[row * GSTR + 64 + q] + bhh[nBase + 64 + q];
        const float* girow = gi + (size_t)m * H3 + nBase;
        const float r = sigm(girow[q] + ghr);
        const float z = sigm(girow[32 + q] + ghz);
        const float n = tanhf(girow[64 + q] + r * ghn);
        const int qg = qBase + q;
        const float hp = hpf[(size_t)m * Hv + qg];
        const float h = (1.f - z) * n + z * hp;
        hout[(size_t)m * Hv + qg] = h;
        hbf[(size_t)m * Hv + qg] = __float2bfloat16(h);
    }
}

// ---------------- prep kernels -------------------------------------------------
__global__ void gather_x(const float* __restrict__ embed,
                         const int* __restrict__ target) {
    int row = blockIdx.x;              // row = t*B + b
    int t = row >> 10;
    int b = row & (Bv - 1);
    int idx = (t == 0) ? 0 : target[b * Tv + (t - 1)];
    float4 v = ((const float4*)(embed + (size_t)idx * Ev))[threadIdx.x];
    uint2 o = make_uint2(f2bf2(v.x, v.y), f2bf2(v.z, v.w));
    ((uint2*)(g_Xb + (size_t)row * Ev))[threadIdx.x] = o;
}

__global__ void permute_w(const float* __restrict__ Wih, const float* __restrict__ Whh,
                          const float* __restrict__ bih, const float* __restrict__ bhh) {
    int p = blockIdx.x;                // 0..1535
    int T = p / 96, local = p - T * 96;
    int gate = local / 32, q = T * 32 + (local - gate * 32);
    int src = gate * Hv + q;
    int t = threadIdx.x;               // 128 threads
    if (t < 64) {
        float4 v = ((const float4*)(Wih + (size_t)src * Ev))[t];
        ((uint2*)(g_Wih_b + (size_t)p * Ev))[t] =
            make_uint2(f2bf2(v.x, v.y), f2bf2(v.z, v.w));
    }
    float4 w = ((const float4*)(Whh + (size_t)src * Hv))[t];
    ((uint2*)(g_Whh_b + (size_t)p * Hv))[t] =
        make_uint2(f2bf2(w.x, w.y), f2bf2(w.z, w.w));
    if (t == 0) { g_bih_p[p] = bih[src]; g_bhh_p[p] = bhh[src]; }
}

__global__ void conv_outw(const float* __restrict__ W) {
    size_t i = ((size_t)blockIdx.x * 256 + threadIdx.x) * 4;
    float4 v = *(const float4*)(W + i);
    *(uint2*)(g_Wout_b + i) = make_uint2(f2bf2(v.x, v.y), f2bf2(v.z, v.w));
}

__global__ void conv_ctx(const float* __restrict__ ctx) {
    size_t i = ((size_t)blockIdx.x * 256 + threadIdx.x) * 4;
    float4 v = *(const float4*)(ctx + i);
    *(uint2*)(g_Hbf + i) = make_uint2(f2bf2(v.x, v.y), f2bf2(v.z, v.w));
}

// ---------------- log-softmax with smem row cache ------------------------------
__global__ void __launch_bounds__(256)
logsoftmax_rows(float* __restrict__ out) {
    extern __shared__ float rowc[];     // Vv floats
    __shared__ float sm[256], ss[256];
    const int tid = threadIdx.x;
    float* p = out + (size_t)blockIdx.x * Vv;

    float m = -INFINITY, s = 0.f;
    for (int i = tid; i < Vv; i += 256) {
        float x = p[i];
        rowc[i] = x;
        if (x > m) { s = s * expf(m - x) + 1.f; m = x; }
        else       { s += expf(x - m); }
    }
    sm[tid] = m; ss[tid] = s;
    __syncthreads();
    for (int st = 128; st > 0; st >>= 1) {
        if (tid < st) {
            float m2 = sm[tid + st], s2 = ss[tid + st];
            float M = fmaxf(sm[tid], m2);
            ss[tid] = ss[tid] * expf(sm[tid] - M) + s2 * expf(m2 - M);
            sm[tid] = M;
        }
        __syncthreads();
    }
    const float lse = sm[0] + logf(ss[0]);
    for (int i = tid; i < Vv; i += 256) p[i] = rowc[i] - lse;
}

// ---------------- launch --------------------------------------------------------
extern "C" void kernel_launch(void* const* d_in, const int* in_sizes, int n_in,
                              void* d_out, int out_size) {
    const float* context = (const float*)d_in[0];
    const int*   target  = (const int*)  d_in[1];
    const float* embed   = (const float*)d_in[2];
    const float* W_ih    = (const float*)d_in[3];
    const float* W_hh    = (const float*)d_in[4];
    const float* b_ih    = (const float*)d_in[5];
    const float* b_hh    = (const float*)d_in[6];
    const float* out_W   = (const float*)d_in[7];
    const float* out_b   = (const float*)d_in[8];
    float* out = (float*)d_out;

    float *pGI, *pHall, *pbih, *pbhh;
    __nv_bfloat16 *pXb, *pHbf, *pWihb, *pWhhb, *pWoutb;
    cudaGetSymbolAddress((void**)&pXb, g_Xb);
    cudaGetSymbolAddress((void**)&pGI, g_GI);
    cudaGetSymbolAddress((void**)&pHall, g_Hall);
    cudaGetSymbolAddress((void**)&pHbf, g_Hbf);
    cudaGetSymbolAddress((void**)&pWihb, g_Wih_b);
    cudaGetSymbolAddress((void**)&pWhhb, g_Whh_b);
    cudaGetSymbolAddress((void**)&pWoutb, g_Wout_b);
    cudaGetSymbolAddress((void**)&pbih, g_bih_p);
    cudaGetSymbolAddress((void**)&pbhh, g_bhh_p);

    const int SMEMBF  = 3 * (128 + 128) * 20 * 4;   // 61440
    const int SMEMREC = 3 * (64 + 96) * 36 * 4;     // 69120
    const int SMEMSFT = Vv * 4;                      // 32000
    cudaFuncSetAttribute(bf_gemm<0>,
                         cudaFuncAttributeMaxDynamicSharedMemorySize, SMEMBF);
    cudaFuncSetAttribute(bf_gemm<1>,
                         cudaFuncAttributeMaxDynamicSharedMemorySize, SMEMBF);
    cudaFuncSetAttribute(rec_step,
                         cudaFuncAttributeMaxDynamicSharedMemorySize, SMEMREC);
    cudaFuncSetAttribute(logsoftmax_rows,
                         cudaFuncAttributeMaxDynamicSharedMemorySize, SMEMSFT);

    // 0) prep: permute/convert weights, gather+convert inputs, context->bf16
    permute_w<<<H3, 128>>>(W_ih, W_hh, b_ih, b_hh);
    conv_outw<<<(Vv * Hv) / 1024, 256>>>(out_W);
    gather_x<<<Tv * Bv, 64>>>(embed, target);
    conv_ctx<<<(Bv * Hv) / 1024, 256>>>(context);

    // 1) GI = X @ Wih^T + bih (bf16): (16384, 1536, K=256)
    bf_gemm<0><<<dim3(H3 / 128, (Tv * Bv) / 128), 256, SMEMBF>>>(
        pXb, pWihb, pbih, pGI, Tv * Bv, H3, Ev);

    // 2) recurrence: fused bf16 GEMM + gates per step (grid 16 x 16)
    for (int t = 0; t < Tv; t++) {
        const float* hpf = (t == 0) ? context : (pHall + (size_t)(t - 1) * Bv * Hv);
        rec_step<<<dim3(H3 / 96, Bv / 64), 256, SMEMREC>>>(
            pHbf + (size_t)t * Bv * Hv, pWhhb, pGI + (size_t)t * Bv * H3, hpf,
            pHall + (size_t)t * Bv * Hv, pHbf + (size_t)(t + 1) * Bv * Hv, pbhh);
    }

    // 3) logits (bf16): (16384, 8000, K=512), remapped rows; A = Hbf slices 1..16
    bf_gemm<1><<<dim3((Vv + 127) / 128, (Tv * Bv) / 128), 256, SMEMBF>>>(
        pHbf + (size_t)Bv * Hv, pWoutb, out_b, out, Tv * Bv, Vv, Hv);

    // 4) in-place log-softmax per (b,t) row
    logsoftmax_rows<<<Bv * Tv, 256, SMEMSFT>>>(out);
}

// round 6
// speedup vs baseline: 5.5288x; 1.1430x over previous
#include <cuda_runtime.h>
#include <cuda_bf16.h>
#include <math.h>
#include <stdint.h>

#define Bv 1024
#define Tv 16
#define Vv 8000
#define Ev 256
#define Hv 512
#define H3 1536

// ---------------- scratch (static device globals) ----------------------------
__device__ __nv_bfloat16 g_Xb[Tv * Bv * Ev];           // gathered inputs (bf16)
__device__ float g_GI[(size_t)Tv * Bv * H3];           // permuted input gates
__device__ float g_Hall[Tv * Bv * Hv];                 // hidden states (fp32 carry)
__device__ __nv_bfloat16 g_Hbf[(Tv + 1) * Bv * Hv];    // slice0=context, t+1=step t
__device__ __nv_bfloat16 g_Wih_b[H3 * Ev];             // permuted W_ih (bf16)
__device__ __nv_bfloat16 g_Whh_b[H3 * Hv];             // permuted W_hh (bf16)
__device__ __nv_bfloat16 g_Wout_b[Vv * Hv];            // out_W (bf16)
__device__ float g_bih_p[H3];
__device__ float g_bhh_p[H3];

// ---------------- helpers ------------------------------------------------------
__device__ __forceinline__ uint32_t smem_u32(const void* p) {
    uint32_t a;
    asm("{ .reg .u64 t; cvta.to.shared.u64 t, %1; cvt.u32.u64 %0, t; }"
        : "=r"(a) : "l"(p));
    return a;
}
__device__ __forceinline__ uint32_t f2bf2(float lo, float hi) {
    uint32_t r;
    asm("cvt.rn.bf16x2.f32 %0, %1, %2;" : "=r"(r) : "f"(hi), "f"(lo));
    return r;
}
__device__ __forceinline__ void cp_async16(uint32_t dst, const void* src, uint32_t sz) {
    asm volatile("cp.async.cg.shared.global [%0], [%1], 16, %2;"
                 :: "r"(dst), "l"(src), "r"(sz) : "memory");
}
__device__ __forceinline__ void cp_commit() {
    asm volatile("cp.async.commit_group;" ::: "memory");
}
__device__ __forceinline__ void cp_wait1() {
    asm volatile("cp.async.wait_group 1;" ::: "memory");
}
__device__ __forceinline__ void ldm_x4(uint32_t* r, uint32_t addr) {
    asm volatile("ldmatrix.sync.aligned.m8n8.x4.shared.b16 {%0,%1,%2,%3}, [%4];"
                 : "=r"(r[0]), "=r"(r[1]), "=r"(r[2]), "=r"(r[3]) : "r"(addr));
}
__device__ __forceinline__ void ldm_x2(uint32_t* r, uint32_t addr) {
    asm volatile("ldmatrix.sync.aligned.m8n8.x2.shared.b16 {%0,%1}, [%2];"
                 : "=r"(r[0]), "=r"(r[1]) : "r"(addr));
}
__device__ __forceinline__ void mma_bf16(float* c, const uint32_t* a, const uint32_t* b) {
    asm volatile(
        "mma.sync.aligned.m16n8k16.row.col.f32.bf16.bf16.f32 "
        "{%0,%1,%2,%3}, {%4,%5,%6,%7}, {%8,%9}, {%0,%1,%2,%3};"
        : "+f"(c[0]), "+f"(c[1]), "+f"(c[2]), "+f"(c[3])
        : "r"(a[0]), "r"(a[1]), "r"(a[2]), "r"(a[3]), "r"(b[0]), "r"(b[1]));
}
__device__ __forceinline__ float sigm(float x) { return 1.f / (1.f + expf(-x)); }

// ================== bf16 GEMM (ldmatrix + m16n8k16, BK=64, 3-stage) ============
// C[m,n] = sum_k A[m,k]*W[n,k] + bias[n]   (A: MxK bf16, W: NxK bf16, K%64==0)
// MODE 0: plain (GI).  MODE 1: row remap (t*B+b)->(b*T+t) (logits).
template <int MODE>
__global__ void __launch_bounds__(256)
bf_gemm(const __nv_bfloat16* __restrict__ A, const __nv_bfloat16* __restrict__ W,
        const float* __restrict__ bias, float* __restrict__ C,
        int M, int N, int K) {
    constexpr int BM = 128, BN = 128, STAGES = 3;
    constexpr int RSTR = 36;                 // u32 per smem row (32 data + 4 pad)
    constexpr int ASTG = BM * RSTR;          // u32 per stage
    constexpr int BSTG = BN * RSTR;

    extern __shared__ uint32_t smu[];
    const uint32_t sA = smem_u32(smu);
    const uint32_t sB = sA + STAGES * ASTG * 4;

    const int tid = threadIdx.x;
    const int wid = tid >> 5, lane = tid & 31;
    const int grp = lane >> 2, tig = lane & 3;
    const int warpRow = wid >> 2, warpCol = wid & 3;
    const int mBase = blockIdx.y * BM;
    const int nBase = blockIdx.x * BN;

    auto load_stage = [&](int s, int kc) {
        const int k0 = kc * 64;
#pragma unroll
        for (int i = 0; i < 4; i++) {                   // A: 1024 x 16B
            int idx = i * 256 + tid;
            int row = idx >> 3, c = idx & 7;
            cp_async16(sA + (s * ASTG + row * RSTR + c * 4) * 4,
                       A + (size_t)(mBase + row) * K + k0 + c * 8, 16);
        }
#pragma unroll
        for (int i = 0; i < 4; i++) {                   // B: 1024 x 16B
            int idx = i * 256 + tid;
            int row = idx >> 3, c = idx & 7;
            int g = nBase + row;
            uint32_t ok = (g < N) ? 16u : 0u;
            if (g >= N) g = 0;
            cp_async16(sB + (s * BSTG + row * RSTR + c * 4) * 4,
                       W + (size_t)g * K + k0 + c * 8, ok);
        }
    };

    // ldmatrix per-thread base offsets (bytes, stage-relative)
    const int a_r = lane & 15, a_c = (lane >> 4) * 4;              // A x4
    const int b_r = (lane >> 4) * 8 + (lane & 7), b_c = ((lane >> 3) & 1) * 4;
    uint32_t aOff[4], bOff[2];
#pragma unroll
    for (int mt = 0; mt < 4; mt++)
        aOff[mt] = ((warpRow * 64 + mt * 16 + a_r) * RSTR + a_c) * 4;
#pragma unroll
    for (int nb = 0; nb < 2; nb++)
        bOff[nb] = ((warpCol * 32 + nb * 16 + b_r) * RSTR + b_c) * 4;

    float acc[4][4][4];
#pragma unroll
    for (int mt = 0; mt < 4; mt++)
#pragma unroll
        for (int nt = 0; nt < 4; nt++)
#pragma unroll
            for (int j = 0; j < 4; j++) acc[mt][nt][j] = 0.f;

    const int nk = K >> 6;
    load_stage(0, 0); cp_commit();
    load_stage(1, 1); cp_commit();

    for (int k = 0; k < nk; k++) {
        const int s = k % STAGES;
        cp_wait1();
        __syncthreads();
        if (k + 2 < nk) load_stage((k + 2) % STAGES, k + 2);
        cp_commit();

        const uint32_t aS = sA + s * ASTG * 4;
        const uint32_t bS = sB + s * BSTG * 4;
#pragma unroll
        for (int kk = 0; kk < 4; kk++) {                // four k16 slices (32B apart)
            uint32_t a[4][4], b[2][4];
#pragma unroll
            for (int mt = 0; mt < 4; mt++) ldm_x4(a[mt], aS + aOff[mt] + kk * 32);
#pragma unroll
            for (int nb = 0; nb < 2; nb++) ldm_x4(b[nb], bS + bOff[nb] + kk * 32);
#pragma unroll
            for (int mt = 0; mt < 4; mt++)
#pragma unroll
                for (int nt = 0; nt < 4; nt++)
                    mma_bf16(acc[mt][nt], a[mt], &b[nt >> 1][(nt & 1) * 2]);
        }
    }

    // epilogue: bias + store (optional row remap)
#pragma unroll
    for (int mt = 0; mt < 4; mt++) {
        const int m0 = mBase + warpRow * 64 + mt * 16 + grp;
        const int m1 = m0 + 8;
        const int r0 = (MODE == 1) ? ((m0 & (Bv - 1)) * Tv + (m0 >> 10)) : m0;
        const int r1 = (MODE == 1) ? ((m1 & (Bv - 1)) * Tv + (m1 >> 10)) : m1;
        float* c0 = C + (size_t)r0 * N;
        float* c1 = C + (size_t)r1 * N;
#pragma unroll
        for (int nt = 0; nt < 4; nt++) {
            const int n = nBase + warpCol * 32 + nt * 8 + tig * 2;
            if (n < N) {
                float2 bv = *(const float2*)(bias + n);
                *(float2*)(c0 + n) = make_float2(acc[mt][nt][0] + bv.x,
                                                 acc[mt][nt][1] + bv.y);
                *(float2*)(c1 + n) = make_float2(acc[mt][nt][2] + bv.x,
                                                 acc[mt][nt][3] + bv.y);
            }
        }
    }
}

// ================== bf16 recurrence GEMM + fused GRU gates =====================
// BM=64, BN=96 ([r32|z32|n32] blocks), BK=64. A = hprev bf16, W = Whh_b.
__global__ void __launch_bounds__(256)
rec_step(const __nv_bfloat16* __restrict__ A, const __nv_bfloat16* __restrict__ W,
         const float* __restrict__ gi, const float* __restrict__ hpf,
         float* __restrict__ hout, __nv_bfloat16* __restrict__ hbf,
         const float* __restrict__ bhh) {
    constexpr int STAGES = 3, RSTR = 36;     // 32 data u32 + 4 pad (BK=64 bf16)
    constexpr int ASTG = 64 * RSTR, BSTG = 96 * RSTR;
    constexpr int K = Hv;

    extern __shared__ uint32_t smu[];
    const uint32_t sA = smem_u32(smu);
    const uint32_t sB = sA + STAGES * ASTG * 4;

    const int tid = threadIdx.x;
    const int wid = tid >> 5, lane = tid & 31;
    const int grp = lane >> 2, tig = lane & 3;
    const int warpRow = wid >> 2, warpCol = wid & 3;   // 2 x 4, warp tile 32x24
    const int mBase = blockIdx.y * 64;
    const int nBase = blockIdx.x * 96;

    auto load_stage = [&](int s, int kc) {
        const int k0 = kc * 64;
#pragma unroll
        for (int i = 0; i < 2; i++) {                   // A: 512 x 16B
            int idx = i * 256 + tid;
            int row = idx >> 3, c = idx & 7;
            cp_async16(sA + (s * ASTG + row * RSTR + c * 4) * 4,
                       A + (size_t)(mBase + row) * K + k0 + c * 8, 16);
        }
#pragma unroll
        for (int i = 0; i < 3; i++) {                   // B: 768 x 16B
            int idx = i * 256 + tid;
            int row = idx >> 3, c = idx & 7;
            cp_async16(sB + (s * BSTG + row * RSTR + c * 4) * 4,
                       W + (size_t)(nBase + row) * K + k0 + c * 8, 16);
        }
    };

    const int a_r = lane & 15, a_c = (lane >> 4) * 4;
    const int b_r = (lane >> 4) * 8 + (lane & 7), b_c = ((lane >> 3) & 1) * 4;
    const int b2_r = lane & 7, b2_c = ((lane >> 3) & 1) * 4;   // x2 (lanes 0-15)
    uint32_t aOff[2], bOff, b2Off;
#pragma unroll
    for (int mt = 0; mt < 2; mt++)
        aOff[mt] = ((warpRow * 32 + mt * 16 + a_r) * RSTR + a_c) * 4;
    bOff  = ((warpCol * 24 + b_r) * RSTR + b_c) * 4;
    b2Off = ((warpCol * 24 + 16 + b2_r) * RSTR + b2_c) * 4;

    float acc[2][3][4];
#pragma unroll
    for (int mt = 0; mt < 2; mt++)
#pragma unroll
        for (int nt = 0; nt < 3; nt++)
#pragma unroll
            for (int j = 0; j < 4; j++) acc[mt][nt][j] = 0.f;

    const int nk = K >> 6;                    // 8
    load_stage(0, 0); cp_commit();
    load_stage(1, 1); cp_commit();

    for (int k = 0; k < nk; k++) {
        const int s = k % STAGES;
        cp_wait1();
        __syncthreads();
        if (k + 2 < nk) load_stage((k + 2) % STAGES, k + 2);
        cp_commit();

        const uint32_t aS = sA + s * ASTG * 4;
        const uint32_t bS = sB + s * BSTG * 4;
#pragma unroll
        for (int kk = 0; kk < 4; kk++) {
            uint32_t a[2][4], b01[4], b2[2];
#pragma unroll
            for (int mt = 0; mt < 2; mt++) ldm_x4(a[mt], aS + aOff[mt] + kk * 32);
            ldm_x4(b01, bS + bOff + kk * 32);
            ldm_x2(b2, bS + b2Off + kk * 32);
#pragma unroll
            for (int mt = 0; mt < 2; mt++) {
                mma_bf16(acc[mt][0], a[mt], &b01[0]);
                mma_bf16(acc[mt][1], a[mt], &b01[2]);
                mma_bf16(acc[mt][2], a[mt], b2);
            }
        }
    }

    // -------- epilogue: stage GH to smem, fused gate math --------
    constexpr int GSTR = 100;
    float* gh = (float*)smu;
    asm volatile("cp.async.wait_all;" ::: "memory");
    __syncthreads();
#pragma unroll
    for (int mt = 0; mt < 2; mt++) {
        const int r0 = warpRow * 32 + mt * 16 + grp;
#pragma unroll
        for (int nt = 0; nt < 3; nt++) {
            const int n = warpCol * 24 + nt * 8 + tig * 2;
            gh[r0 * GSTR + n] = acc[mt][nt][0];
            gh[r0 * GSTR + n + 1] = acc[mt][nt][1];
            gh[(r0 + 8) * GSTR + n] = acc[mt][nt][2];
            gh[(r0 + 8) * GSTR + n + 1] = acc[mt][nt][3];
        }
    }
    __syncthreads();
    const int qBase = nBase / 3;              // nBase = bx*96 -> q base = bx*32
#pragma unroll
    for (int i = 0; i < 8; i++) {
        const int idx = i * 256 + tid;        // 0..2047
        const int row = idx >> 5;
        const int q = idx & 31;
        const int m = mBase + row;
        const float ghr = gh[row * GSTR + q] + bhh[nBase + q];
        const float ghz = gh[row * GSTR + 32 + q] + bhh[nBase + 32 + q];
        const float ghn = gh[row * GSTR + 64 + q] + bhh[nBase + 64 + q];
        const float* girow = gi + (size_t)m * H3 + nBase;
        const float r = sigm(girow[q] + ghr);
        const float z = sigm(girow[32 + q] + ghz);
        const float n = tanhf(girow[64 + q] + r * ghn);
        const int qg = qBase + q;
        const float hp = hpf[(size_t)m * Hv + qg];
        const float h = (1.f - z) * n + z * hp;
        hout[(size_t)m * Hv + qg] = h;
        hbf[(size_t)m * Hv + qg] = __float2bfloat16(h);
    }
}

// ---------------- prep kernels -------------------------------------------------
__global__ void gather_x(const float* __restrict__ embed,
                         const int* __restrict__ target) {
    int row = blockIdx.x;              // row = t*B + b
    int t = row >> 10;
    int b = row & (Bv - 1);
    int idx = (t == 0) ? 0 : target[b * Tv + (t - 1)];
    float4 v = ((const float4*)(embed + (size_t)idx * Ev))[threadIdx.x];
    uint2 o = make_uint2(f2bf2(v.x, v.y), f2bf2(v.z, v.w));
    ((uint2*)(g_Xb + (size_t)row * Ev))[threadIdx.x] = o;
}

__global__ void permute_w(const float* __restrict__ Wih, const float* __restrict__ Whh,
                          const float* __restrict__ bih, const float* __restrict__ bhh) {
    int p = blockIdx.x;                // 0..1535
    int T = p / 96, local = p - T * 96;
    int gate = local / 32, q = T * 32 + (local - gate * 32);
    int src = gate * Hv + q;
    int t = threadIdx.x;               // 128 threads
    if (t < 64) {
        float4 v = ((const float4*)(Wih + (size_t)src * Ev))[t];
        ((uint2*)(g_Wih_b + (size_t)p * Ev))[t] =
            make_uint2(f2bf2(v.x, v.y), f2bf2(v.z, v.w));
    }
    float4 w = ((const float4*)(Whh + (size_t)src * Hv))[t];
    ((uint2*)(g_Whh_b + (size_t)p * Hv))[t] =
        make_uint2(f2bf2(w.x, w.y), f2bf2(w.z, w.w));
    if (t == 0) { g_bih_p[p] = bih[src]; g_bhh_p[p] = bhh[src]; }
}

__global__ void conv_outw(const float* __restrict__ W) {
    size_t i = ((size_t)blockIdx.x * 256 + threadIdx.x) * 4;
    float4 v = *(const float4*)(W + i);
    *(uint2*)(g_Wout_b + i) = make_uint2(f2bf2(v.x, v.y), f2bf2(v.z, v.w));
}

__global__ void conv_ctx(const float* __restrict__ ctx) {
    size_t i = ((size_t)blockIdx.x * 256 + threadIdx.x) * 4;
    float4 v = *(const float4*)(ctx + i);
    *(uint2*)(g_Hbf + i) = make_uint2(f2bf2(v.x, v.y), f2bf2(v.z, v.w));
}

// ---------------- log-softmax, float4 path, smem row cache ---------------------
__global__ void __launch_bounds__(256)
logsoftmax_rows(float* __restrict__ out) {
    extern __shared__ float4 rowc4[];   // 2000 float4 = 8000 floats
    __shared__ float sm[256], ss[256];
    const int tid = threadIdx.x;
    float4* p4 = (float4*)(out + (size_t)blockIdx.x * Vv);

    float m = -INFINITY, s = 0.f;
    for (int i = tid; i < Vv / 4; i += 256) {
        float4 x = p4[i];
        rowc4[i] = x;
        float mx = fmaxf(fmaxf(x.x, x.y), fmaxf(x.z, x.w));
        if (mx > m) {
            s = s * expf(m - mx);
            m = mx;
        }
        s += expf(x.x - m) + expf(x.y - m) + expf(x.z - m) + expf(x.w - m);
    }
    sm[tid] = m; ss[tid] = s;
    __syncthreads();
    for (int st = 128; st > 0; st >>= 1) {
        if (tid < st) {
            float m2 = sm[tid + st], s2 = ss[tid + st];
            float M = fmaxf(sm[tid], m2);
            ss[tid] = ss[tid] * expf(sm[tid] - M) + s2 * expf(m2 - M);
            sm[tid] = M;
        }
        __syncthreads();
    }
    const float lse = sm[0] + logf(ss[0]);
    for (int i = tid; i < Vv / 4; i += 256) {
        float4 x = rowc4[i];
        p4[i] = make_float4(x.x - lse, x.y - lse, x.z - lse, x.w - lse);
    }
}

// ---------------- launch --------------------------------------------------------
extern "C" void kernel_launch(void* const* d_in, const int* in_sizes, int n_in,
                              void* d_out, int out_size) {
    const float* context = (const float*)d_in[0];
    const int*   target  = (const int*)  d_in[1];
    const float* embed   = (const float*)d_in[2];
    const float* W_ih    = (const float*)d_in[3];
    const float* W_hh    = (const float*)d_in[4];
    const float* b_ih    = (const float*)d_in[5];
    const float* b_hh    = (const float*)d_in[6];
    const float* out_W   = (const float*)d_in[7];
    const float* out_b   = (const float*)d_in[8];
    float* out = (float*)d_out;

    float *pGI, *pHall, *pbih, *pbhh;
    __nv_bfloat16 *pXb, *pHbf, *pWihb, *pWhhb, *pWoutb;
    cudaGetSymbolAddress((void**)&pXb, g_Xb);
    cudaGetSymbolAddress((void**)&pGI, g_GI);
    cudaGetSymbolAddress((void**)&pHall, g_Hall);
    cudaGetSymbolAddress((void**)&pHbf, g_Hbf);
    cudaGetSymbolAddress((void**)&pWihb, g_Wih_b);
    cudaGetSymbolAddress((void**)&pWhhb, g_Whh_b);
    cudaGetSymbolAddress((void**)&pWoutb, g_Wout_b);
    cudaGetSymbolAddress((void**)&pbih, g_bih_p);
    cudaGetSymbolAddress((void**)&pbhh, g_bhh_p);

    const int SMEMBF  = 3 * (128 + 128) * 36 * 4;   // 110592
    const int SMEMREC = 3 * (64 + 96) * 36 * 4;     // 69120
    const int SMEMSFT = Vv * 4;                      // 32000
    cudaFuncSetAttribute(bf_gemm<0>,
                         cudaFuncAttributeMaxDynamicSharedMemorySize, SMEMBF);
    cudaFuncSetAttribute(bf_gemm<1>,
                         cudaFuncAttributeMaxDynamicSharedMemorySize, SMEMBF);
    cudaFuncSetAttribute(rec_step,
                         cudaFuncAttributeMaxDynamicSharedMemorySize, SMEMREC);
    cudaFuncSetAttribute(logsoftmax_rows,
                         cudaFuncAttributeMaxDynamicSharedMemorySize, SMEMSFT);

    // 0) prep: permute/convert weights, gather+convert inputs, context->bf16
    permute_w<<<H3, 128>>>(W_ih, W_hh, b_ih, b_hh);
    conv_outw<<<(Vv * Hv) / 1024, 256>>>(out_W);
    gather_x<<<Tv * Bv, 64>>>(embed, target);
    conv_ctx<<<(Bv * Hv) / 1024, 256>>>(context);

    // 1) GI = X @ Wih^T + bih (bf16): (16384, 1536, K=256)
    bf_gemm<0><<<dim3(H3 / 128, (Tv * Bv) / 128), 256, SMEMBF>>>(
        pXb, pWihb, pbih, pGI, Tv * Bv, H3, Ev);

    // 2) recurrence: fused bf16 GEMM + gates per step (grid 16 x 16)
    for (int t = 0; t < Tv; t++) {
        const float* hpf = (t == 0) ? context : (pHall + (size_t)(t - 1) * Bv * Hv);
        rec_step<<<dim3(H3 / 96, Bv / 64), 256, SMEMREC>>>(
            pHbf + (size_t)t * Bv * Hv, pWhhb, pGI + (size_t)t * Bv * H3, hpf,
            pHall + (size_t)t * Bv * Hv, pHbf + (size_t)(t + 1) * Bv * Hv, pbhh);
    }

    // 3) logits (bf16): (16384, 8000, K=512), remapped rows; A = Hbf slices 1..16
    bf_gemm<1><<<dim3((Vv + 127) / 128, (Tv * Bv) / 128), 256, SMEMBF>>>(
        pHbf + (size_t)Bv * Hv, pWoutb, out_b, out, Tv * Bv, Vv, Hv);

    // 4) in-place log-softmax per (b,t) row
    logsoftmax_rows<<<Bv * Tv, 256, SMEMSFT>>>(out);
}